// round 4
// baseline (speedup 1.0000x reference)
#include <cuda_runtime.h>
#include <cuda_bf16.h>
#include <cstdint>
#include <math.h>

// ---------------- problem constants ----------------
#define BB 2
#define HH 240
#define WW 1216
#define CHN 27
#define OC 81
#define OCP 96          // padded N
#define KPAD 256        // padded K (243 real)
#define HWSZ (HH*WW)
#define NPIX (BB*HWSZ)

#define BSTR 528        // B smem row stride bytes (256*2 + 16)
#define ASTR 272        // A smem row stride bytes (128*2 + 16)
#define BBY (OCP*BSTR)  // 50688 per split term

// ---------------- device scratch ----------------
__device__ float g_conv[(size_t)OC * NPIX];                // conv output planes [oc][b][y][x]
__device__ __align__(16) uint8_t g_B[2 * BBY];             // padded bf16 weights [oc][k]: hi || lo

// ---------------- smem layout ----------------
#define SM_BIAS 0                      // 96 floats = 384
#define SM_AH   384
#define SM_AL   (384 + 128*ASTR)       // 384+34816 = 35200
#define SM_BH   (SM_AL + 128*ASTR)     // 70016
#define SM_BL   (SM_BH + BBY)          // 120704
#define SM_TOTAL (SM_BL + BBY)         // 171392

// ---------------- helpers ----------------
__device__ __forceinline__ uint32_t smem_u32(const void* p) {
    uint32_t a;
    asm("{ .reg .u64 t; cvta.to.shared.u64 t, %1; cvt.u32.u64 %0, t; }" : "=r"(a) : "l"(p));
    return a;
}
__device__ __forceinline__ void ldsm4(uint32_t* r, uint32_t a) {
    asm volatile("ldmatrix.sync.aligned.m8n8.x4.shared.b16 {%0,%1,%2,%3}, [%4];"
                 : "=r"(r[0]), "=r"(r[1]), "=r"(r[2]), "=r"(r[3]) : "r"(a));
}
__device__ __forceinline__ void mma16816(float* d, const uint32_t* a, const uint32_t* b) {
    asm volatile("mma.sync.aligned.m16n8k16.row.col.f32.bf16.bf16.f32 "
                 "{%0,%1,%2,%3}, {%4,%5,%6,%7}, {%8,%9}, {%0,%1,%2,%3};"
                 : "+f"(d[0]), "+f"(d[1]), "+f"(d[2]), "+f"(d[3])
                 : "r"(a[0]), "r"(a[1]), "r"(a[2]), "r"(a[3]), "r"(b[0]), "r"(b[1]));
}

// ---------------- prep: weights -> padded bf16 hi/lo [oc][k], k=(tap*27+c) ----------------
__global__ void prep_kernel(const float* __restrict__ conv_w) {
    int idx = blockIdx.x * 256 + threadIdx.x;
    if (idx >= OCP * KPAD) return;
    int oc = idx >> 8;
    int k = idx & 255;
    float v = 0.f;
    if (oc < OC && k < 243) {
        int t = k / 27, c = k - 27 * t;
        int ky = t / 3, kx = t - 3 * ky;
        v = conv_w[((oc * CHN + c) * 3 + ky) * 3 + kx];
    }
    __nv_bfloat16 h = __float2bfloat16(v);
    __nv_bfloat16 l = __float2bfloat16(v - __bfloat162float(h));
    uint32_t off = (uint32_t)oc * BSTR + (uint32_t)k * 2;
    *(__nv_bfloat16*)(g_B + off) = h;
    *(__nv_bfloat16*)(g_B + BBY + off) = l;
}

// ---------------- conv via mma.sync bf16x3: tile 128 px x 96 oc x K256 ----------------
__global__ __launch_bounds__(256, 1)
void conv_tc_kernel(const float* __restrict__ guide, const float* __restrict__ conv_b) {
    extern __shared__ uint8_t smem[];
    const int tid = threadIdx.x;
    const int wid = tid >> 5;
    const int lane = tid & 31;
    const int x0 = blockIdx.x * 128;
    const int y = blockIdx.y;
    const int b = blockIdx.z;

    // B copy (hi||lo contiguous in gmem and smem)
    {
        const uint4* src = (const uint4*)g_B;
        uint4* dst = (uint4*)(smem + SM_BH);
        #pragma unroll 4
        for (int i = tid; i < (2 * BBY) / 16; i += 256) dst[i] = src[i];
    }
    if (tid < OCP) ((float*)(smem + SM_BIAS))[tid] = (tid < OC) ? conv_b[tid] : 0.f;

    const int mwarp = wid & 3;           // M32 block
    const int nwarp = wid >> 2;          // N48 block
    float acc[2][6][4];
    #pragma unroll
    for (int j = 0; j < 2; j++)
        #pragma unroll
        for (int n = 0; n < 6; n++)
            #pragma unroll
            for (int q = 0; q < 4; q++) acc[j][n][q] = 0.f;

    for (int stage = 0; stage < 2; stage++) {
        const int kbase = stage * 128;
        __syncthreads();   // previous-stage A fully consumed

        // ---- A im2col stage: rows=pixels (lane), k-octets per warp-task ----
        #pragma unroll 1
        for (int it = 0; it < 8; it++) {
            int t = wid + 8 * it;        // 0..63
            int koct = t & 15;
            int rblk = t >> 4;
            int row = rblk * 32 + lane;
            int x = x0 + row;
            union { uint4 u; __nv_bfloat16 h[8]; } hv, lv;
            #pragma unroll
            for (int i = 0; i < 8; i++) {
                int k = kbase + koct * 8 + i;
                float v = 0.f;
                if (k < 243) {
                    int tt = k / 27, c = k - 27 * tt;
                    int ky = tt / 3, kx = tt - 3 * ky;
                    int yy = y + ky - 1;
                    int xx = x + kx - 1;
                    if (yy >= 0 && yy < HH && (unsigned)xx < WW)
                        v = __ldg(&guide[((size_t)(b * CHN + c) * HH + yy) * WW + xx]);
                }
                __nv_bfloat16 h = __float2bfloat16(v);
                hv.h[i] = h;
                lv.h[i] = __float2bfloat16(v - __bfloat162float(h));
            }
            uint32_t ao = (uint32_t)row * ASTR + (uint32_t)koct * 16;
            *(uint4*)(smem + SM_AH + ao) = hv.u;
            *(uint4*)(smem + SM_AL + ao) = lv.u;
        }
        __syncthreads();

        // ---- mma over 8 k16 chunks ----
        #pragma unroll 1
        for (int kc = 0; kc < 8; kc++) {
            const int kg = kbase + kc * 16;
            uint32_t a_h[2][4], a_l[2][4], b_h[6][2], b_l[6][2];

            // A fragments (hi, lo)
            #pragma unroll
            for (int j = 0; j < 2; j++) {
                uint32_t ao = (uint32_t)(mwarp * 32 + j * 16 + (lane & 15)) * ASTR
                            + (uint32_t)(kc * 16 + (lane >> 4) * 8) * 2;
                ldsm4(a_h[j], smem_u32(smem + SM_AH + ao));
                ldsm4(a_l[j], smem_u32(smem + SM_AL + ao));
            }
            // B fragments (hi, lo): pair p covers ntiles 2p, 2p+1
            #pragma unroll
            for (int p = 0; p < 3; p++) {
                int ocr = nwarp * 48 + p * 16 + (lane & 7) + ((lane >> 4) << 3);
                uint32_t bo = (uint32_t)ocr * BSTR + (uint32_t)(kg + ((lane >> 3) & 1) * 8) * 2;
                uint32_t r[4];
                ldsm4(r, smem_u32(smem + SM_BH + bo));
                b_h[2*p][0] = r[0]; b_h[2*p][1] = r[1];
                b_h[2*p+1][0] = r[2]; b_h[2*p+1][1] = r[3];
                ldsm4(r, smem_u32(smem + SM_BL + bo));
                b_l[2*p][0] = r[0]; b_l[2*p][1] = r[1];
                b_l[2*p+1][0] = r[2]; b_l[2*p+1][1] = r[3];
            }
            // three split terms
            #pragma unroll
            for (int j = 0; j < 2; j++)
                #pragma unroll
                for (int n = 0; n < 6; n++) mma16816(acc[j][n], a_h[j], b_h[n]);
            #pragma unroll
            for (int j = 0; j < 2; j++)
                #pragma unroll
                for (int n = 0; n < 6; n++) mma16816(acc[j][n], a_h[j], b_l[n]);
            #pragma unroll
            for (int j = 0; j < 2; j++)
                #pragma unroll
                for (int n = 0; n < 6; n++) mma16816(acc[j][n], a_l[j], b_h[n]);
        }
    }

    // ---- epilogue: add bias, store plane-major ----
    const int gid = lane >> 2, t4 = lane & 3;
    const float* bias = (const float*)(smem + SM_BIAS);
    const size_t base = (size_t)b * HWSZ + (size_t)y * WW;
    #pragma unroll
    for (int j = 0; j < 2; j++) {
        int xa = x0 + mwarp * 32 + j * 16 + gid;
        int xb2 = xa + 8;
        #pragma unroll
        for (int n = 0; n < 6; n++) {
            int oc = nwarp * 48 + n * 8 + t4 * 2;
            float b0 = bias[oc], b1 = bias[oc + 1];
            if (oc < OC) {
                if (xa < WW)  g_conv[(size_t)oc * NPIX + base + xa]  = acc[j][n][0] + b0;
                if (xb2 < WW) g_conv[(size_t)oc * NPIX + base + xb2] = acc[j][n][2] + b0;
            }
            if (oc + 1 < OC) {
                if (xa < WW)  g_conv[(size_t)(oc + 1) * NPIX + base + xa]  = acc[j][n][1] + b1;
                if (xb2 < WW) g_conv[(size_t)(oc + 1) * NPIX + base + xb2] = acc[j][n][3] + b1;
            }
        }
    }
}

// ---------------- propagation: softmax + bilinear-zeros + confidence blend ----------------
__global__ void prop_kernel(const float* __restrict__ prev,
                            const float* __restrict__ sp_dep,
                            const float* __restrict__ confid,
                            const float* __restrict__ tap,
                            float* __restrict__ out_cur,
                            float* __restrict__ pred_out,
                            const float* __restrict__ feat_src,
                            float* __restrict__ feat_dst,
                            int iter) {
    int p = blockIdx.x * blockDim.x + threadIdx.x;
    if (p >= NPIX) return;
    int b = p / HWSZ;
    int rem = p % HWSZ;
    int y = rem / WW;
    int x = rem % WW;
    const float* img = prev + (size_t)b * HWSZ;

    float araw[9];
    #pragma unroll
    for (int t = 0; t < 9; t++)
        araw[t] = g_conv[(size_t)(54 + iter * 9 + t) * NPIX + p];
    float mx = araw[0];
    #pragma unroll
    for (int t = 1; t < 9; t++) mx = fmaxf(mx, araw[t]);
    float wv[9];
    float s = 0.f;
    #pragma unroll
    for (int t = 0; t < 9; t++) { wv[t] = __expf(araw[t] - mx); s += wv[t]; }
    float inv = 1.f / s;

    float agg = 0.f;
    #pragma unroll
    for (int t = 0; t < 9; t++) {
        float ox = g_conv[(size_t)((iter * 9 + t) * 2) * NPIX + p];
        float oy = g_conv[(size_t)((iter * 9 + t) * 2 + 1) * NPIX + p];
        float px = ox + tap[2 * t] + (float)x;
        float py = oy + tap[2 * t + 1] + (float)y;
        float x0f = floorf(px), y0f = floorf(py);
        int xi = (int)x0f, yi = (int)y0f;
        float wx = px - x0f, wy = py - y0f;

        float v00 = 0.f, v01 = 0.f, v10 = 0.f, v11 = 0.f;
        bool xa = (xi >= 0) & (xi < WW);
        bool xb2 = (xi + 1 >= 0) & (xi + 1 < WW);
        bool ya = (yi >= 0) & (yi < HH);
        bool yb = (yi + 1 >= 0) & (yi + 1 < HH);
        if (ya) {
            const float* r0 = img + (size_t)yi * WW;
            if (xa) v00 = r0[xi];
            if (xb2) v01 = r0[xi + 1];
        }
        if (yb) {
            const float* r1 = img + (size_t)(yi + 1) * WW;
            if (xa) v10 = r1[xi];
            if (xb2) v11 = r1[xi + 1];
        }
        float v = (1.f - wy) * ((1.f - wx) * v00 + wx * v01)
                + wy * ((1.f - wx) * v10 + wx * v11);
        agg += wv[t] * v;
    }
    agg *= inv;

    float sp = sp_dep[p];
    float cf = 1.f / (1.f + __expf(-confid[p]));
    float sg = (sp > 0.f) ? 1.f : ((sp < 0.f) ? -1.f : 0.f);
    cf *= sg;
    float o = (1.f - cf) * agg + cf * sp;

    out_cur[p] = o;
    if (pred_out) pred_out[p] = o;
    if (feat_dst) feat_dst[p] = feat_src[p];
}

// ---------------- launch ----------------
extern "C" void kernel_launch(void* const* d_in, const int* in_sizes, int n_in,
                              void* d_out, int out_size) {
    const float* input  = (const float*)d_in[0];
    const float* guide  = (const float*)d_in[1];
    const float* sp_dep = (const float*)d_in[2];
    const float* confid = (const float*)d_in[3];
    const float* conv_w = (const float*)d_in[4];
    const float* conv_b = (const float*)d_in[5];
    const float* tap    = (const float*)d_in[6];

    float* out = (float*)d_out;
    float* pred = out;
    float* feat = out + NPIX;
    float* inter = out + 2 * (size_t)NPIX;

    static bool attr_set = false;
    if (!attr_set) {
        cudaFuncSetAttribute(conv_tc_kernel, cudaFuncAttributeMaxDynamicSharedMemorySize, SM_TOTAL);
        attr_set = true;
    }

    prep_kernel<<<(OCP * KPAD + 255) / 256, 256>>>(conv_w);

    dim3 cgrid((WW + 127) / 128, HH, BB);
    conv_tc_kernel<<<cgrid, 256, SM_TOTAL>>>(guide, conv_b);

    int pb = (NPIX + 255) / 256;
    prop_kernel<<<pb, 256>>>(input, sp_dep, confid, tap, inter, nullptr, input, feat, 0);
    prop_kernel<<<pb, 256>>>(inter, sp_dep, confid, tap, inter + NPIX, nullptr, nullptr, nullptr, 1);
    prop_kernel<<<pb, 256>>>(inter + NPIX, sp_dep, confid, tap, inter + 2 * (size_t)NPIX, pred, nullptr, nullptr, 2);
}

// round 5
// speedup vs baseline: 1.7652x; 1.7652x over previous
#include <cuda_runtime.h>
#include <cstdint>
#include <math.h>

// ---------------- problem constants ----------------
#define BB 2
#define HH 240
#define WW 1216
#define CHN 27
#define OC 81
#define HWSZ (HH*WW)
#define NPIX (BB*HWSZ)

#define TX 32            // tiles per CTA in x
#define TY 2             // tiles per CTA in y
#define GX 19            // 608/32
#define GY 60            // 120/2
#define OCG 11           // oc per warp group (8*11=88 >= 81)
#define UKB 19008        // bytes per U_k buffer: 27*88*8 (float2 dup)

// ---------------- device scratch ----------------
__device__ float g_conv[(size_t)OC * NPIX];                  // conv output planes [oc][b][y][x]
__device__ __align__(16) float2 g_U[16 * 27 * 88];           // Winograd weights, duplicated float2

// ---------------- smem layout (bytes) ----------------
#define SM_BIAS 0                         // 88 floats -> 384
#define SM_PATCH 384                      // 27*6*68*4 = 44064
#define SM_V (384 + 44064)                // 44448; 16*27*64*4 = 110592
#define SM_U (SM_V + 110592)              // 155040; 2*19008 = 38016
#define SM_TOTAL (SM_U + 2*UKB)           // 193056

typedef unsigned long long ull;

// ---------------- helpers ----------------
__device__ __forceinline__ uint32_t smem_u32(const void* p) {
    uint32_t a;
    asm("{ .reg .u64 t; cvta.to.shared.u64 t, %1; cvt.u32.u64 %0, t; }" : "=r"(a) : "l"(p));
    return a;
}
__device__ __forceinline__ ull packdup(float v) {
    ull r; unsigned u = __float_as_uint(v);
    asm("mov.b64 %0, {%1, %1};" : "=l"(r) : "r"(u));
    return r;
}
__device__ __forceinline__ float2 unpack2(ull v) {
    unsigned lo, hi;
    asm("mov.b64 {%0, %1}, %2;" : "=r"(lo), "=r"(hi) : "l"(v));
    return make_float2(__uint_as_float(lo), __uint_as_float(hi));
}
#define FMA2(accv, av, bv) asm("fma.rn.f32x2 %0, %1, %2, %0;" : "+l"(accv) : "l"(av), "l"(bv))
#define CP16(dst, src) asm volatile("cp.async.ca.shared.global [%0], [%1], 16;" :: "r"(dst), "l"(src))
#define CP_COMMIT() asm volatile("cp.async.commit_group;")
#define CP_WAIT1() asm volatile("cp.async.wait_group 1;")
#define CP_WAIT0() asm volatile("cp.async.wait_group 0;")

// ---------------- prep: U = G g G^T, duplicated float2, [k][c][88] ----------------
__global__ void prep_kernel(const float* __restrict__ conv_w) {
    int idx = blockIdx.x * 256 + threadIdx.x;
    if (idx >= 27 * 88) return;
    int c = idx / 88;
    int oc = idx % 88;
    float U[4][4];
    if (oc < OC) {
        float g[3][3];
        #pragma unroll
        for (int ky = 0; ky < 3; ky++)
            #pragma unroll
            for (int kx = 0; kx < 3; kx++)
                g[ky][kx] = conv_w[((oc * CHN + c) * 3 + ky) * 3 + kx];
        float T[4][3];
        #pragma unroll
        for (int kx = 0; kx < 3; kx++) {
            T[0][kx] = g[0][kx];
            T[1][kx] = 0.5f * (g[0][kx] + g[1][kx] + g[2][kx]);
            T[2][kx] = 0.5f * (g[0][kx] - g[1][kx] + g[2][kx]);
            T[3][kx] = g[2][kx];
        }
        #pragma unroll
        for (int r = 0; r < 4; r++) {
            U[r][0] = T[r][0];
            U[r][1] = 0.5f * (T[r][0] + T[r][1] + T[r][2]);
            U[r][2] = 0.5f * (T[r][0] - T[r][1] + T[r][2]);
            U[r][3] = T[r][2];
        }
    } else {
        #pragma unroll
        for (int r = 0; r < 4; r++)
            #pragma unroll
            for (int s = 0; s < 4; s++) U[r][s] = 0.f;
    }
    #pragma unroll
    for (int r = 0; r < 4; r++)
        #pragma unroll
        for (int s = 0; s < 4; s++) {
            int k = r * 4 + s;
            float v = U[r][s];
            g_U[(k * 27 + c) * 88 + oc] = make_float2(v, v);
        }
}

// ---------------- Winograd conv kernel ----------------
__global__ __launch_bounds__(256, 1)
void wino_kernel(const float* __restrict__ guide, const float* __restrict__ conv_b) {
    extern __shared__ uint8_t smem[];
    const uint32_t sbase = smem_u32(smem);
    const int tid = threadIdx.x;
    const int wid = tid >> 5;
    const int lane = tid & 31;
    const int bx = blockIdx.x, by = blockIdx.y, bz = blockIdx.z;

    // --- prefetch U_0 via cp.async ASAP ---
    {
        const char* src = (const char*)g_U;
        uint32_t dst = sbase + SM_U;
        for (int j = tid; j < UKB / 16; j += 256)
            CP16(dst + j * 16, src + j * 16);
        CP_COMMIT();
    }

    // --- bias ---
    if (tid < 88) ((float*)(smem + SM_BIAS))[tid] = (tid < OC) ? conv_b[tid] : 0.f;

    // --- stage input patch: 27 ch x 6 rows x 66 cols (zero-padded) ---
    {
        const int py0 = 4 * by - 1;
        const int px0 = 64 * bx - 1;
        float* patch = (float*)(smem + SM_PATCH);
        for (int i = tid; i < 27 * 6 * 66; i += 256) {
            int c = i / 396;
            int rr = (i / 66) % 6;
            int xx = i % 66;
            int gy = py0 + rr;
            int gx = px0 + xx;
            float v = 0.f;
            if ((unsigned)gy < HH && (unsigned)gx < WW)
                v = __ldg(&guide[((size_t)(bz * CHN + c) * HH + gy) * WW + gx]);
            patch[(c * 6 + rr) * 68 + xx] = v;
        }
    }
    __syncthreads();

    // --- input transform V = B^T d B, scatter to V[k][c][pair] ---
    {
        const float* patch = (const float*)(smem + SM_PATCH);
        float* V = (float*)(smem + SM_V);
        for (int i = tid; i < 27 * 64; i += 256) {
            int c = i >> 6;
            int t = i & 63;
            int tx = t & 31;
            int tyl = t >> 5;
            const float* base = patch + (c * 6 + tyl * 2) * 68 + 2 * tx;
            float d[4][4];
            #pragma unroll
            for (int r = 0; r < 4; r++) {
                float2 p0 = *(const float2*)(base + r * 68);
                float2 p1 = *(const float2*)(base + r * 68 + 2);
                d[r][0] = p0.x; d[r][1] = p0.y; d[r][2] = p1.x; d[r][3] = p1.y;
            }
            float R[4][4];
            #pragma unroll
            for (int r = 0; r < 4; r++) {
                R[r][0] = d[r][0] - d[r][2];
                R[r][1] = d[r][1] + d[r][2];
                R[r][2] = d[r][2] - d[r][1];
                R[r][3] = d[r][1] - d[r][3];
            }
            int pair = 2 * tx + tyl;
            #pragma unroll
            for (int s = 0; s < 4; s++) {
                float e0 = R[0][s] - R[2][s];
                float e1 = R[1][s] + R[2][s];
                float e2 = R[2][s] - R[1][s];
                float e3 = R[1][s] - R[3][s];
                V[((0 * 4 + s) * 27 + c) * 64 + pair] = e0;
                V[((1 * 4 + s) * 27 + c) * 64 + pair] = e1;
                V[((2 * 4 + s) * 27 + c) * 64 + pair] = e2;
                V[((3 * 4 + s) * 27 + c) * 64 + pair] = e3;
            }
        }
    }
    __syncthreads();

    // --- 16 position-GEMMs with fused output transform ---
    ull Y[4 * OCG];
    #pragma unroll
    for (int j = 0; j < 4 * OCG; j++) Y[j] = 0ull;

    #pragma unroll 1
    for (int k = 0; k < 16; k++) {
        if (k + 1 < 16) {
            const char* src = (const char*)g_U + (size_t)(k + 1) * UKB;
            uint32_t dst = sbase + SM_U + ((k + 1) & 1) * UKB;
            for (int j = tid; j < UKB / 16; j += 256)
                CP16(dst + j * 16, src + j * 16);
            CP_COMMIT();
            CP_WAIT1();
        } else {
            CP_WAIT0();
        }
        __syncthreads();

        const ull* Us = (const ull*)(smem + SM_U + (k & 1) * UKB) + wid * OCG;
        const float* Vk = (const float*)(smem + SM_V) + k * 27 * 64 + 2 * lane;

        ull m[OCG];
        #pragma unroll
        for (int j = 0; j < OCG; j++) m[j] = 0ull;

        #pragma unroll 3
        for (int c = 0; c < 27; c++) {
            ull v = *(const ull*)(Vk + c * 64);
            const ull* ur = Us + c * 88;
            #pragma unroll
            for (int j = 0; j < OCG; j++) FMA2(m[j], ur[j], v);
        }

        // output-transform accumulation: coef(p,q) = A_p[r]*A_q[s]
        int r = k >> 2, s = k & 3;
        float A0r = (r == 3) ? 0.f : 1.f;
        float A1r = (r == 0) ? 0.f : ((r == 1) ? 1.f : -1.f);
        float A0s = (s == 3) ? 0.f : 1.f;
        float A1s = (s == 0) ? 0.f : ((s == 1) ? 1.f : -1.f);
        float c00 = A0r * A0s, c01 = A0r * A1s, c10 = A1r * A0s, c11 = A1r * A1s;
        if (c00 != 0.f) {
            ull cd = packdup(c00);
            #pragma unroll
            for (int j = 0; j < OCG; j++) FMA2(Y[4 * j + 0], cd, m[j]);
        }
        if (c01 != 0.f) {
            ull cd = packdup(c01);
            #pragma unroll
            for (int j = 0; j < OCG; j++) FMA2(Y[4 * j + 1], cd, m[j]);
        }
        if (c10 != 0.f) {
            ull cd = packdup(c10);
            #pragma unroll
            for (int j = 0; j < OCG; j++) FMA2(Y[4 * j + 2], cd, m[j]);
        }
        if (c11 != 0.f) {
            ull cd = packdup(c11);
            #pragma unroll
            for (int j = 0; j < OCG; j++) FMA2(Y[4 * j + 3], cd, m[j]);
        }
        __syncthreads();
    }

    // --- epilogue: add bias, store float2 rows into plane-major g_conv ---
    {
        const float* bias = (const float*)(smem + SM_BIAS);
        const int ybase = 4 * by;
        const int x = 2 * (32 * bx + lane);
        const size_t base = (size_t)bz * HWSZ + x;
        #pragma unroll
        for (int j = 0; j < OCG; j++) {
            int oc = wid * OCG + j;
            if (oc >= OC) break;
            float bv = bias[oc];
            float2 p0q0 = unpack2(Y[4 * j + 0]);   // (tyl0, tyl1) for out (p=0,q=0)
            float2 p0q1 = unpack2(Y[4 * j + 1]);
            float2 p1q0 = unpack2(Y[4 * j + 2]);
            float2 p1q1 = unpack2(Y[4 * j + 3]);
            float* plane = g_conv + (size_t)oc * NPIX + base;
            *(float2*)(plane + (size_t)(ybase + 0) * WW) = make_float2(p0q0.x + bv, p0q1.x + bv);
            *(float2*)(plane + (size_t)(ybase + 1) * WW) = make_float2(p1q0.x + bv, p1q1.x + bv);
            *(float2*)(plane + (size_t)(ybase + 2) * WW) = make_float2(p0q0.y + bv, p0q1.y + bv);
            *(float2*)(plane + (size_t)(ybase + 3) * WW) = make_float2(p1q0.y + bv, p1q1.y + bv);
        }
    }
}

// ---------------- propagation: softmax + bilinear-zeros + confidence blend ----------------
__global__ void prop_kernel(const float* __restrict__ prev,
                            const float* __restrict__ sp_dep,
                            const float* __restrict__ confid,
                            const float* __restrict__ tap,
                            float* __restrict__ out_cur,
                            float* __restrict__ pred_out,
                            const float* __restrict__ feat_src,
                            float* __restrict__ feat_dst,
                            int iter) {
    int p = blockIdx.x * blockDim.x + threadIdx.x;
    if (p >= NPIX) return;
    int b = p / HWSZ;
    int rem = p % HWSZ;
    int y = rem / WW;
    int x = rem % WW;
    const float* img = prev + (size_t)b * HWSZ;

    float araw[9];
    #pragma unroll
    for (int t = 0; t < 9; t++)
        araw[t] = g_conv[(size_t)(54 + iter * 9 + t) * NPIX + p];
    float mx = araw[0];
    #pragma unroll
    for (int t = 1; t < 9; t++) mx = fmaxf(mx, araw[t]);
    float wv[9];
    float s = 0.f;
    #pragma unroll
    for (int t = 0; t < 9; t++) { wv[t] = __expf(araw[t] - mx); s += wv[t]; }
    float inv = 1.f / s;

    float agg = 0.f;
    #pragma unroll
    for (int t = 0; t < 9; t++) {
        float ox = g_conv[(size_t)((iter * 9 + t) * 2) * NPIX + p];
        float oy = g_conv[(size_t)((iter * 9 + t) * 2 + 1) * NPIX + p];
        float px = ox + tap[2 * t] + (float)x;
        float py = oy + tap[2 * t + 1] + (float)y;
        float x0f = floorf(px), y0f = floorf(py);
        int xi = (int)x0f, yi = (int)y0f;
        float wx = px - x0f, wy = py - y0f;

        float v00 = 0.f, v01 = 0.f, v10 = 0.f, v11 = 0.f;
        bool xa = (xi >= 0) & (xi < WW);
        bool xb2 = (xi + 1 >= 0) & (xi + 1 < WW);
        bool ya = (yi >= 0) & (yi < HH);
        bool yb = (yi + 1 >= 0) & (yi + 1 < HH);
        if (ya) {
            const float* r0 = img + (size_t)yi * WW;
            if (xa) v00 = r0[xi];
            if (xb2) v01 = r0[xi + 1];
        }
        if (yb) {
            const float* r1 = img + (size_t)(yi + 1) * WW;
            if (xa) v10 = r1[xi];
            if (xb2) v11 = r1[xi + 1];
        }
        float v = (1.f - wy) * ((1.f - wx) * v00 + wx * v01)
                + wy * ((1.f - wx) * v10 + wx * v11);
        agg += wv[t] * v;
    }
    agg *= inv;

    float sp = sp_dep[p];
    float cf = 1.f / (1.f + __expf(-confid[p]));
    float sg = (sp > 0.f) ? 1.f : ((sp < 0.f) ? -1.f : 0.f);
    cf *= sg;
    float o = (1.f - cf) * agg + cf * sp;

    out_cur[p] = o;
    if (pred_out) pred_out[p] = o;
    if (feat_dst) feat_dst[p] = feat_src[p];
}

// ---------------- launch ----------------
extern "C" void kernel_launch(void* const* d_in, const int* in_sizes, int n_in,
                              void* d_out, int out_size) {
    const float* input  = (const float*)d_in[0];
    const float* guide  = (const float*)d_in[1];
    const float* sp_dep = (const float*)d_in[2];
    const float* confid = (const float*)d_in[3];
    const float* conv_w = (const float*)d_in[4];
    const float* conv_b = (const float*)d_in[5];
    const float* tap    = (const float*)d_in[6];

    float* out = (float*)d_out;
    float* pred = out;
    float* feat = out + NPIX;
    float* inter = out + 2 * (size_t)NPIX;

    static bool attr_set = false;
    if (!attr_set) {
        cudaFuncSetAttribute(wino_kernel, cudaFuncAttributeMaxDynamicSharedMemorySize, SM_TOTAL);
        attr_set = true;
    }

    prep_kernel<<<(27 * 88 + 255) / 256, 256>>>(conv_w);

    dim3 wgrid(GX, GY, BB);
    wino_kernel<<<wgrid, 256, SM_TOTAL>>>(guide, conv_b);

    int pb = (NPIX + 255) / 256;
    prop_kernel<<<pb, 256>>>(input, sp_dep, confid, tap, inter, nullptr, input, feat, 0);
    prop_kernel<<<pb, 256>>>(inter, sp_dep, confid, tap, inter + NPIX, nullptr, nullptr, nullptr, 1);
    prop_kernel<<<pb, 256>>>(inter + NPIX, sp_dep, confid, tap, inter + 2 * (size_t)NPIX, pred, nullptr, nullptr, 2);
}

// round 7
// speedup vs baseline: 1.9447x; 1.1017x over previous
#include <cuda_runtime.h>
#include <cstdint>
#include <math.h>

// ---------------- problem constants ----------------
#define BB 2
#define HH 240
#define WW 1216
#define CHN 27
#define OC 81
#define HWSZ (HH*WW)
#define NPIX (BB*HWSZ)

#define GX 19            // 1216/64
#define GY 60            // 240/4
#define UOC 96           // padded oc stride in U
#define UKB (27*UOC*4)   // 10368 bytes per U_k buffer

// ---------------- device scratch ----------------
__device__ float g_conv[(size_t)OC * NPIX];              // conv output planes [oc][b][y][x]
__device__ __align__(16) float g_U[16 * 27 * UOC];       // Winograd weights [k][c][96]

// ---------------- smem layout (bytes) ----------------
#define SM_BIAS 0                          // 96 floats -> 384
#define SM_PATCH 384                       // 27*6*68*4 = 44064
#define SM_V (384 + 44064)                 // 44448; 16*27*64*4 = 110592
#define SM_U (SM_V + 110592)               // 155040; 2*10368 = 20736
#define SM_TOTAL (SM_U + 2*UKB)            // 175776

// ---------------- helpers ----------------
#define CP16(dst, src) asm volatile("cp.async.ca.shared.global [%0], [%1], 16;" :: "r"(dst), "l"(src))
#define CP_COMMIT() asm volatile("cp.async.commit_group;")
#define CP_WAIT1() asm volatile("cp.async.wait_group 1;")
#define CP_WAIT0() asm volatile("cp.async.wait_group 0;")

__device__ __forceinline__ uint32_t smem_u32(const void* p) {
    uint32_t a;
    asm("{ .reg .u64 t; cvta.to.shared.u64 t, %1; cvt.u32.u64 %0, t; }" : "=r"(a) : "l"(p));
    return a;
}

// ---------------- prep: U = G g G^T, [k][c][96] plain float ----------------
__global__ void prep_kernel(const float* __restrict__ conv_w) {
    int idx = blockIdx.x * 256 + threadIdx.x;
    if (idx >= 27 * UOC) return;
    int c = idx / UOC;
    int oc = idx % UOC;
    float U[4][4];
    if (oc < OC) {
        float g[3][3];
        #pragma unroll
        for (int ky = 0; ky < 3; ky++)
            #pragma unroll
            for (int kx = 0; kx < 3; kx++)
                g[ky][kx] = conv_w[((oc * CHN + c) * 3 + ky) * 3 + kx];
        float T[4][3];
        #pragma unroll
        for (int kx = 0; kx < 3; kx++) {
            T[0][kx] = g[0][kx];
            T[1][kx] = 0.5f * (g[0][kx] + g[1][kx] + g[2][kx]);
            T[2][kx] = 0.5f * (g[0][kx] - g[1][kx] + g[2][kx]);
            T[3][kx] = g[2][kx];
        }
        #pragma unroll
        for (int r = 0; r < 4; r++) {
            U[r][0] = T[r][0];
            U[r][1] = 0.5f * (T[r][0] + T[r][1] + T[r][2]);
            U[r][2] = 0.5f * (T[r][0] - T[r][1] + T[r][2]);
            U[r][3] = T[r][2];
        }
    } else {
        #pragma unroll
        for (int r = 0; r < 4; r++)
            #pragma unroll
            for (int s = 0; s < 4; s++) U[r][s] = 0.f;
    }
    #pragma unroll
    for (int r = 0; r < 4; r++)
        #pragma unroll
        for (int s = 0; s < 4; s++)
            g_U[((r * 4 + s) * 27 + c) * UOC + oc] = U[r][s];
}

// ---------------- GEMM inner: m[j] += U[c][ocb+j] * V[c] over 27 c ----------------
template<int CNT>
__device__ __forceinline__ void gemm27(const float2* __restrict__ Vk,
                                       const float* __restrict__ Uk,
                                       float2* __restrict__ m) {
    #pragma unroll
    for (int j = 0; j < CNT; j++) m[j] = make_float2(0.f, 0.f);
    #pragma unroll 3
    for (int c = 0; c < 27; c++) {
        float2 v = Vk[c * 32];
        const float* u = Uk + c * UOC;
        #pragma unroll
        for (int j = 0; j < CNT; j++) {
            m[j].x = fmaf(u[j], v.x, m[j].x);
            m[j].y = fmaf(u[j], v.y, m[j].y);
        }
    }
}

// ---------------- Winograd conv kernel: 512 threads, 16 warps ----------------
__global__ __launch_bounds__(512, 1)
void wino_kernel(const float* __restrict__ guide, const float* __restrict__ conv_b) {
    extern __shared__ uint8_t smem[];
    const uint32_t sbase = smem_u32(smem);
    const int tid = threadIdx.x;
    const int wid = tid >> 5;
    const int lane = tid & 31;
    const int bx = blockIdx.x, by = blockIdx.y, bz = blockIdx.z;

    // oc assignment: warp 0 -> 6 oc, warps 1..15 -> 5 oc (81 exact)
    const int ocb = (wid == 0) ? 0 : 6 + (wid - 1) * 5;
    const int cnt = (wid == 0) ? 6 : 5;

    // --- prefetch U_0 ---
    {
        const char* src = (const char*)g_U;
        uint32_t dst = sbase + SM_U;
        for (int j = tid; j < UKB / 16; j += 512)
            CP16(dst + j * 16, src + (size_t)j * 16);
        CP_COMMIT();
    }

    if (tid < UOC) ((float*)(smem + SM_BIAS))[tid] = (tid < OC) ? conv_b[tid] : 0.f;

    // --- stage input patch: 27 ch x 6 rows x 66 cols (zero-padded), stride 68 ---
    {
        const int py0 = 4 * by - 1;
        const int px0 = 64 * bx - 1;
        float* patch = (float*)(smem + SM_PATCH);
        for (int i = tid; i < 27 * 6 * 66; i += 512) {
            int c = i / 396;
            int rr = (i / 66) % 6;
            int xx = i % 66;
            int gy = py0 + rr;
            int gx = px0 + xx;
            float v = 0.f;
            if ((unsigned)gy < HH && (unsigned)gx < WW)
                v = __ldg(&guide[((size_t)(bz * CHN + c) * HH + gy) * WW + gx]);
            patch[(c * 6 + rr) * 68 + xx] = v;
        }
    }
    __syncthreads();

    // --- input transform V = B^T d B; pair index p = tx + 32*tyl ---
    {
        const float* patch = (const float*)(smem + SM_PATCH);
        float* V = (float*)(smem + SM_V);
        for (int i = tid; i < 27 * 64; i += 512) {
            int c = i >> 6;
            int t = i & 63;
            int tx = t & 31;
            int tyl = t >> 5;
            const float* base = patch + (c * 6 + tyl * 2) * 68 + 2 * tx;
            float d[4][4];
            #pragma unroll
            for (int r = 0; r < 4; r++) {
                float2 p0 = *(const float2*)(base + r * 68);
                float2 p1 = *(const float2*)(base + r * 68 + 2);
                d[r][0] = p0.x; d[r][1] = p0.y; d[r][2] = p1.x; d[r][3] = p1.y;
            }
            float R[4][4];
            #pragma unroll
            for (int r = 0; r < 4; r++) {
                R[r][0] = d[r][0] - d[r][2];
                R[r][1] = d[r][1] + d[r][2];
                R[r][2] = d[r][2] - d[r][1];
                R[r][3] = d[r][1] - d[r][3];
            }
            #pragma unroll
            for (int s = 0; s < 4; s++) {
                V[((0 * 4 + s) * 27 + c) * 64 + t] = R[0][s] - R[2][s];
                V[((1 * 4 + s) * 27 + c) * 64 + t] = R[1][s] + R[2][s];
                V[((2 * 4 + s) * 27 + c) * 64 + t] = R[2][s] - R[1][s];
                V[((3 * 4 + s) * 27 + c) * 64 + t] = R[1][s] - R[3][s];
            }
        }
    }
    __syncthreads();

    // --- 16 position-GEMMs with fused output transform ---
    float2 Y[4][6];
    #pragma unroll
    for (int q = 0; q < 4; q++)
        #pragma unroll
        for (int j = 0; j < 6; j++) Y[q][j] = make_float2(0.f, 0.f);

    #pragma unroll 1
    for (int k = 0; k < 16; k++) {
        if (k + 1 < 16) {
            const char* src = (const char*)g_U + (size_t)(k + 1) * UKB;
            uint32_t dst = sbase + SM_U + ((k + 1) & 1) * UKB;
            for (int j = tid; j < UKB / 16; j += 512)
                CP16(dst + j * 16, src + j * 16);
            CP_COMMIT();
            CP_WAIT1();
        } else {
            CP_WAIT0();
        }
        __syncthreads();

        const float* Uk = (const float*)(smem + SM_U + (k & 1) * UKB) + ocb;
        const float2* Vk = (const float2*)(smem + SM_V) + k * 27 * 32 + lane;

        float2 m[6];
        if (cnt == 6) gemm27<6>(Vk, Uk, m);
        else         gemm27<5>(Vk, Uk, m);

        // output-transform accumulation: coef(p,q) = A_p[r]*A_q[s]
        int r = k >> 2, s = k & 3;
        float A0r = (r == 3) ? 0.f : 1.f;
        float A1r = (r == 0) ? 0.f : ((r == 1) ? 1.f : -1.f);
        float A0s = (s == 3) ? 0.f : 1.f;
        float A1s = (s == 0) ? 0.f : ((s == 1) ? 1.f : -1.f);
        float cc[4] = { A0r * A0s, A0r * A1s, A1r * A0s, A1r * A1s };
        #pragma unroll
        for (int q = 0; q < 4; q++) {
            if (cc[q] != 0.f) {
                #pragma unroll
                for (int j = 0; j < 6; j++) {
                    if (j >= cnt) break;
                    Y[q][j].x = fmaf(cc[q], m[j].x, Y[q][j].x);
                    Y[q][j].y = fmaf(cc[q], m[j].y, Y[q][j].y);
                }
            }
        }
        __syncthreads();
    }

    // --- epilogue: bias + STG.128; thread owns tiles tx0=2*(lane&15), tx0+1 at tyl=lane>>4 ---
    {
        const float* bias = (const float*)(smem + SM_BIAS);
        const int xcol = 64 * bx + 4 * (lane & 15);
        const int row0 = 4 * by + 2 * (lane >> 4);
        const size_t base = (size_t)bz * HWSZ + xcol;
        for (int j = 0; j < cnt; j++) {
            int oc = ocb + j;
            if (oc >= OC) break;
            float bv = bias[oc];
            float* plane = g_conv + (size_t)oc * NPIX + base;
            float4 r0v = make_float4(Y[0][j].x + bv, Y[1][j].x + bv,
                                     Y[0][j].y + bv, Y[1][j].y + bv);
            float4 r1v = make_float4(Y[2][j].x + bv, Y[3][j].x + bv,
                                     Y[2][j].y + bv, Y[3][j].y + bv);
            *(float4*)(plane + (size_t)row0 * WW) = r0v;
            *(float4*)(plane + (size_t)(row0 + 1) * WW) = r1v;
        }
    }
}

// ---------------- propagation: softmax + bilinear-zeros + confidence blend ----------------
__global__ void prop_kernel(const float* __restrict__ prev,
                            const float* __restrict__ sp_dep,
                            const float* __restrict__ confid,
                            const float* __restrict__ tap,
                            float* __restrict__ out_cur,
                            float* __restrict__ pred_out,
                            const float* __restrict__ feat_src,
                            float* __restrict__ feat_dst,
                            int iter) {
    int p = blockIdx.x * blockDim.x + threadIdx.x;
    if (p >= NPIX) return;
    int b = p / HWSZ;
    int rem = p % HWSZ;
    int y = rem / WW;
    int x = rem % WW;
    const float* img = prev + (size_t)b * HWSZ;

    float araw[9];
    #pragma unroll
    for (int t = 0; t < 9; t++)
        araw[t] = g_conv[(size_t)(54 + iter * 9 + t) * NPIX + p];
    float mx = araw[0];
    #pragma unroll
    for (int t = 1; t < 9; t++) mx = fmaxf(mx, araw[t]);
    float wv[9];
    float s = 0.f;
    #pragma unroll
    for (int t = 0; t < 9; t++) { wv[t] = __expf(araw[t] - mx); s += wv[t]; }
    float inv = 1.f / s;

    float agg = 0.f;
    #pragma unroll
    for (int t = 0; t < 9; t++) {
        float ox = g_conv[(size_t)((iter * 9 + t) * 2) * NPIX + p];
        float oy = g_conv[(size_t)((iter * 9 + t) * 2 + 1) * NPIX + p];
        float px = ox + tap[2 * t] + (float)x;
        float py = oy + tap[2 * t + 1] + (float)y;
        float x0f = floorf(px), y0f = floorf(py);
        int xi = (int)x0f, yi = (int)y0f;
        float wx = px - x0f, wy = py - y0f;

        float v00 = 0.f, v01 = 0.f, v10 = 0.f, v11 = 0.f;
        bool xa = (xi >= 0) & (xi < WW);
        bool xb2 = (xi + 1 >= 0) & (xi + 1 < WW);
        bool ya = (yi >= 0) & (yi < HH);
        bool yb = (yi + 1 >= 0) & (yi + 1 < HH);
        if (ya) {
            const float* r0 = img + (size_t)yi * WW;
            if (xa) v00 = r0[xi];
            if (xb2) v01 = r0[xi + 1];
        }
        if (yb) {
            const float* r1 = img + (size_t)(yi + 1) * WW;
            if (xa) v10 = r1[xi];
            if (xb2) v11 = r1[xi + 1];
        }
        float v = (1.f - wy) * ((1.f - wx) * v00 + wx * v01)
                + wy * ((1.f - wx) * v10 + wx * v11);
        agg += wv[t] * v;
    }
    agg *= inv;

    float sp = sp_dep[p];
    float cf = 1.f / (1.f + __expf(-confid[p]));
    float sg = (sp > 0.f) ? 1.f : ((sp < 0.f) ? -1.f : 0.f);
    cf *= sg;
    float o = (1.f - cf) * agg + cf * sp;

    out_cur[p] = o;
    if (pred_out) pred_out[p] = o;
    if (feat_dst) feat_dst[p] = feat_src[p];
}

// ---------------- launch ----------------
extern "C" void kernel_launch(void* const* d_in, const int* in_sizes, int n_in,
                              void* d_out, int out_size) {
    const float* input  = (const float*)d_in[0];
    const float* guide  = (const float*)d_in[1];
    const float* sp_dep = (const float*)d_in[2];
    const float* confid = (const float*)d_in[3];
    const float* conv_w = (const float*)d_in[4];
    const float* conv_b = (const float*)d_in[5];
    const float* tap    = (const float*)d_in[6];

    float* out = (float*)d_out;
    float* pred = out;
    float* feat = out + NPIX;
    float* inter = out + 2 * (size_t)NPIX;

    static bool attr_set = false;
    if (!attr_set) {
        cudaFuncSetAttribute(wino_kernel, cudaFuncAttributeMaxDynamicSharedMemorySize, SM_TOTAL);
        attr_set = true;
    }

    prep_kernel<<<(27 * UOC + 255) / 256, 256>>>(conv_w);

    dim3 wgrid(GX, GY, BB);
    wino_kernel<<<wgrid, 512, SM_TOTAL>>>(guide, conv_b);

    int pb = (NPIX + 255) / 256;
    prop_kernel<<<pb, 256>>>(input, sp_dep, confid, tap, inter, nullptr, input, feat, 0);
    prop_kernel<<<pb, 256>>>(inter, sp_dep, confid, tap, inter + NPIX, nullptr, nullptr, nullptr, 1);
    prop_kernel<<<pb, 256>>>(inter + NPIX, sp_dep, confid, tap, inter + 2 * (size_t)NPIX, pred, nullptr, nullptr, 2);
}

// round 8
// speedup vs baseline: 2.3131x; 1.1894x over previous
#include <cuda_runtime.h>
#include <cstdint>
#include <math.h>

// ---------------- problem constants ----------------
#define BB 2
#define HH 240
#define WW 1216
#define CHN 27
#define OC 81
#define HWSZ (HH*WW)
#define NPIX (BB*HWSZ)

#define GX 19            // 1216/64
#define GY 60            // 240/4
#define UCOL 128         // padded column stride in U (per k,c row)
#define UKB (27*UCOL*4)  // 13824 bytes per U_k buffer

// ---------------- device scratch ----------------
__device__ float g_conv[(size_t)OC * NPIX];              // conv output planes [oc][b][y][x]
__device__ __align__(16) float g_U[16 * 27 * UCOL];      // Winograd weights, warp-permuted

// ---------------- smem layout (bytes) ----------------
#define SM_BIAS 0                          // 96 floats -> 384
#define SM_PATCH 384                       // 27*6*68*4 = 44064
#define SM_V (384 + 44064)                 // 44448; 16*27*64*4 = 110592
#define SM_U (SM_V + 110592)               // 155040 (16B aligned); 2*13824 = 27648
#define SM_TOTAL (SM_U + 2*UKB)            // 182688

// ---------------- helpers ----------------
#define CP16(dst, src) asm volatile("cp.async.ca.shared.global [%0], [%1], 16;" :: "r"(dst), "l"(src))
#define CP_COMMIT() asm volatile("cp.async.commit_group;")
#define CP_WAIT1() asm volatile("cp.async.wait_group 1;")
#define CP_WAIT0() asm volatile("cp.async.wait_group 0;")

__device__ __forceinline__ uint32_t smem_u32(const void* p) {
    uint32_t a;
    asm("{ .reg .u64 t; cvta.to.shared.u64 t, %1; cvt.u32.u64 %0, t; }" : "=r"(a) : "l"(p));
    return a;
}

// ---------------- prep: U = G g G^T, warp-permuted [k][c][128] ----------------
// oc = 6*w + j  ->  column 8*w + j  (w = 0..15, j = 0..5)
__global__ void prep_kernel(const float* __restrict__ conv_w) {
    int idx = blockIdx.x * 256 + threadIdx.x;
    if (idx >= 27 * 96) return;
    int c = idx / 96;
    int oc = idx % 96;
    float U[4][4];
    if (oc < OC) {
        float g[3][3];
        #pragma unroll
        for (int ky = 0; ky < 3; ky++)
            #pragma unroll
            for (int kx = 0; kx < 3; kx++)
                g[ky][kx] = conv_w[((oc * CHN + c) * 3 + ky) * 3 + kx];
        float T[4][3];
        #pragma unroll
        for (int kx = 0; kx < 3; kx++) {
            T[0][kx] = g[0][kx];
            T[1][kx] = 0.5f * (g[0][kx] + g[1][kx] + g[2][kx]);
            T[2][kx] = 0.5f * (g[0][kx] - g[1][kx] + g[2][kx]);
            T[3][kx] = g[2][kx];
        }
        #pragma unroll
        for (int r = 0; r < 4; r++) {
            U[r][0] = T[r][0];
            U[r][1] = 0.5f * (T[r][0] + T[r][1] + T[r][2]);
            U[r][2] = 0.5f * (T[r][0] - T[r][1] + T[r][2]);
            U[r][3] = T[r][2];
        }
    } else {
        #pragma unroll
        for (int r = 0; r < 4; r++)
            #pragma unroll
            for (int s = 0; s < 4; s++) U[r][s] = 0.f;
    }
    int w = oc / 6, j = oc % 6;
    int col = 8 * w + j;
    #pragma unroll
    for (int r = 0; r < 4; r++)
        #pragma unroll
        for (int s = 0; s < 4; s++)
            g_U[((r * 4 + s) * 27 + c) * UCOL + col] = U[r][s];
    // zero the never-written pad columns 8w+6, 8w+7 once (idx mapping reuse)
    if (oc < 32) {   // 16 warps x 2 pad cols
        int w2 = oc >> 1, jp = 6 + (oc & 1);
        #pragma unroll
        for (int k = 0; k < 16; k++)
            g_U[(k * 27 + c) * UCOL + 8 * w2 + jp] = 0.f;
    }
}

// ---------------- Winograd conv kernel: 512 threads, 16 warps x 6 oc ----------------
__global__ __launch_bounds__(512, 1)
void wino_kernel(const float* __restrict__ guide, const float* __restrict__ conv_b) {
    extern __shared__ uint8_t smem[];
    const uint32_t sbase = smem_u32(smem);
    const int tid = threadIdx.x;
    const int wid = tid >> 5;
    const int lane = tid & 31;
    const int bx = blockIdx.x, by = blockIdx.y, bz = blockIdx.z;

    // --- prefetch U_0 ---
    {
        const char* src = (const char*)g_U;
        uint32_t dst = sbase + SM_U;
        for (int j = tid; j < UKB / 16; j += 512)
            CP16(dst + j * 16, src + (size_t)j * 16);
        CP_COMMIT();
    }

    if (tid < 96) ((float*)(smem + SM_BIAS))[tid] = (tid < OC) ? conv_b[tid] : 0.f;

    // --- stage input patch: 27 ch x 6 rows x 66 cols (zero-padded), stride 68 ---
    {
        const int py0 = 4 * by - 1;
        const int px0 = 64 * bx - 1;
        float* patch = (float*)(smem + SM_PATCH);
        for (int i = tid; i < 27 * 6 * 66; i += 512) {
            int c = i / 396;
            int rr = (i / 66) % 6;
            int xx = i % 66;
            int gy = py0 + rr;
            int gx = px0 + xx;
            float v = 0.f;
            if ((unsigned)gy < HH && (unsigned)gx < WW)
                v = __ldg(&guide[((size_t)(bz * CHN + c) * HH + gy) * WW + gx]);
            patch[(c * 6 + rr) * 68 + xx] = v;
        }
    }
    __syncthreads();

    // --- input transform V = B^T d B; pair index t = tx + 32*tyl ---
    {
        const float* patch = (const float*)(smem + SM_PATCH);
        float* V = (float*)(smem + SM_V);
        for (int i = tid; i < 27 * 64; i += 512) {
            int c = i >> 6;
            int t = i & 63;
            int tx = t & 31;
            int tyl = t >> 5;
            const float* base = patch + (c * 6 + tyl * 2) * 68 + 2 * tx;
            float d[4][4];
            #pragma unroll
            for (int r = 0; r < 4; r++) {
                float2 p0 = *(const float2*)(base + r * 68);
                float2 p1 = *(const float2*)(base + r * 68 + 2);
                d[r][0] = p0.x; d[r][1] = p0.y; d[r][2] = p1.x; d[r][3] = p1.y;
            }
            float R[4][4];
            #pragma unroll
            for (int r = 0; r < 4; r++) {
                R[r][0] = d[r][0] - d[r][2];
                R[r][1] = d[r][1] + d[r][2];
                R[r][2] = d[r][2] - d[r][1];
                R[r][3] = d[r][1] - d[r][3];
            }
            #pragma unroll
            for (int s = 0; s < 4; s++) {
                V[((0 * 4 + s) * 27 + c) * 64 + t] = R[0][s] - R[2][s];
                V[((1 * 4 + s) * 27 + c) * 64 + t] = R[1][s] + R[2][s];
                V[((2 * 4 + s) * 27 + c) * 64 + t] = R[2][s] - R[1][s];
                V[((3 * 4 + s) * 27 + c) * 64 + t] = R[1][s] - R[3][s];
            }
        }
    }
    __syncthreads();

    // --- 16 position-GEMMs with fused output transform ---
    float2 Y[4][6];
    #pragma unroll
    for (int q = 0; q < 4; q++)
        #pragma unroll
        for (int j = 0; j < 6; j++) Y[q][j] = make_float2(0.f, 0.f);

    #pragma unroll 1
    for (int k = 0; k < 16; k++) {
        if (k + 1 < 16) {
            const char* src = (const char*)g_U + (size_t)(k + 1) * UKB;
            uint32_t dst = sbase + SM_U + ((k + 1) & 1) * UKB;
            for (int j = tid; j < UKB / 16; j += 512)
                CP16(dst + j * 16, src + j * 16);
            CP_COMMIT();
            CP_WAIT1();
        } else {
            CP_WAIT0();
        }
        __syncthreads();

        const float* Uk = (const float*)(smem + SM_U + (k & 1) * UKB) + wid * 8;
        const float2* Vk = (const float2*)(smem + SM_V) + k * 27 * 32 + lane;

        float2 m[6];
        #pragma unroll
        for (int j = 0; j < 6; j++) m[j] = make_float2(0.f, 0.f);
        #pragma unroll 3
        for (int c = 0; c < 27; c++) {
            float2 v = Vk[c * 32];
            float4 ua = *(const float4*)(Uk + c * UCOL);
            float2 ub = *(const float2*)(Uk + c * UCOL + 4);
            m[0].x = fmaf(ua.x, v.x, m[0].x); m[0].y = fmaf(ua.x, v.y, m[0].y);
            m[1].x = fmaf(ua.y, v.x, m[1].x); m[1].y = fmaf(ua.y, v.y, m[1].y);
            m[2].x = fmaf(ua.z, v.x, m[2].x); m[2].y = fmaf(ua.z, v.y, m[2].y);
            m[3].x = fmaf(ua.w, v.x, m[3].x); m[3].y = fmaf(ua.w, v.y, m[3].y);
            m[4].x = fmaf(ub.x, v.x, m[4].x); m[4].y = fmaf(ub.x, v.y, m[4].y);
            m[5].x = fmaf(ub.y, v.x, m[5].x); m[5].y = fmaf(ub.y, v.y, m[5].y);
        }

        // output-transform accumulation: coef(p,q) = A_p[r]*A_q[s]
        int r = k >> 2, s = k & 3;
        float A0r = (r == 3) ? 0.f : 1.f;
        float A1r = (r == 0) ? 0.f : ((r == 1) ? 1.f : -1.f);
        float A0s = (s == 3) ? 0.f : 1.f;
        float A1s = (s == 0) ? 0.f : ((s == 1) ? 1.f : -1.f);
        float cc[4] = { A0r * A0s, A0r * A1s, A1r * A0s, A1r * A1s };
        #pragma unroll
        for (int q = 0; q < 4; q++) {
            if (cc[q] != 0.f) {
                #pragma unroll
                for (int j = 0; j < 6; j++) {
                    Y[q][j].x = fmaf(cc[q], m[j].x, Y[q][j].x);
                    Y[q][j].y = fmaf(cc[q], m[j].y, Y[q][j].y);
                }
            }
        }
        __syncthreads();
    }

    // --- epilogue: bias + STG.128 ---
    {
        const float* bias = (const float*)(smem + SM_BIAS);
        const int xcol = 64 * bx + 4 * (lane & 15);
        const int row0 = 4 * by + 2 * (lane >> 4);
        const size_t base = (size_t)bz * HWSZ + xcol;
        #pragma unroll
        for (int j = 0; j < 6; j++) {
            int oc = 6 * wid + j;
            if (oc >= OC) break;
            float bv = bias[oc];
            float* plane = g_conv + (size_t)oc * NPIX + base;
            float4 r0v = make_float4(Y[0][j].x + bv, Y[1][j].x + bv,
                                     Y[0][j].y + bv, Y[1][j].y + bv);
            float4 r1v = make_float4(Y[2][j].x + bv, Y[3][j].x + bv,
                                     Y[2][j].y + bv, Y[3][j].y + bv);
            *(float4*)(plane + (size_t)row0 * WW) = r0v;
            *(float4*)(plane + (size_t)(row0 + 1) * WW) = r1v;
        }
    }
}

// ---------------- propagation: softmax + bilinear-zeros + confidence blend ----------------
__device__ __constant__ float TAPX[9] = {-1.f, 0.f, 1.f, -1.f, 0.f, 1.f, -1.f, 0.f, 1.f};
__device__ __constant__ float TAPY[9] = {-1.f, -1.f, -1.f, 0.f, 0.f, 0.f, 1.f, 1.f, 1.f};

__global__ void prop_kernel(const float* __restrict__ prev,
                            const float* __restrict__ sp_dep,
                            const float* __restrict__ confid,
                            float* __restrict__ out_cur,
                            float* __restrict__ pred_out,
                            const float* __restrict__ feat_src,
                            float* __restrict__ feat_dst,
                            int iter) {
    int p = blockIdx.x * blockDim.x + threadIdx.x;
    if (p >= NPIX) return;
    int b = p / HWSZ;
    int rem = p % HWSZ;
    int y = rem / WW;
    int x = rem % WW;
    const float* img = prev + (size_t)b * HWSZ;

    // ---- front-load all independent global reads (max MLP) ----
    float araw[9], ox[9], oy[9];
    #pragma unroll
    for (int t = 0; t < 9; t++)
        araw[t] = __ldg(&g_conv[(size_t)(54 + iter * 9 + t) * NPIX + p]);
    #pragma unroll
    for (int t = 0; t < 9; t++) {
        ox[t] = __ldg(&g_conv[(size_t)((iter * 9 + t) * 2) * NPIX + p]);
        oy[t] = __ldg(&g_conv[(size_t)((iter * 9 + t) * 2 + 1) * NPIX + p]);
    }
    float sp = __ldg(&sp_dep[p]);
    float cfr = __ldg(&confid[p]);

    // softmax weights
    float mx = araw[0];
    #pragma unroll
    for (int t = 1; t < 9; t++) mx = fmaxf(mx, araw[t]);
    float wv[9];
    float s = 0.f;
    #pragma unroll
    for (int t = 0; t < 9; t++) { wv[t] = __expf(araw[t] - mx); s += wv[t]; }
    float inv = 1.f / s;

    float agg = 0.f;
    #pragma unroll
    for (int t = 0; t < 9; t++) {
        float px = ox[t] + TAPX[t] + (float)x;
        float py = oy[t] + TAPY[t] + (float)y;
        float x0f = floorf(px), y0f = floorf(py);
        int xi = (int)x0f, yi = (int)y0f;
        float wx = px - x0f, wy = py - y0f;

        float v00 = 0.f, v01 = 0.f, v10 = 0.f, v11 = 0.f;
        bool xa = (xi >= 0) & (xi < WW);
        bool xb2 = (xi + 1 >= 0) & (xi + 1 < WW);
        bool ya = (yi >= 0) & (yi < HH);
        bool yb = (yi + 1 >= 0) & (yi + 1 < HH);
        if (ya) {
            const float* r0 = img + (size_t)yi * WW;
            if (xa) v00 = __ldg(r0 + xi);
            if (xb2) v01 = __ldg(r0 + xi + 1);
        }
        if (yb) {
            const float* r1 = img + (size_t)(yi + 1) * WW;
            if (xa) v10 = __ldg(r1 + xi);
            if (xb2) v11 = __ldg(r1 + xi + 1);
        }
        float v = (1.f - wy) * ((1.f - wx) * v00 + wx * v01)
                + wy * ((1.f - wx) * v10 + wx * v11);
        agg += wv[t] * v;
    }
    agg *= inv;

    float cf = 1.f / (1.f + __expf(-cfr));
    float sg = (sp > 0.f) ? 1.f : ((sp < 0.f) ? -1.f : 0.f);
    cf *= sg;
    float o = (1.f - cf) * agg + cf * sp;

    out_cur[p] = o;
    if (pred_out) pred_out[p] = o;
    if (feat_dst) feat_dst[p] = feat_src[p];
}

// ---------------- launch ----------------
extern "C" void kernel_launch(void* const* d_in, const int* in_sizes, int n_in,
                              void* d_out, int out_size) {
    const float* input  = (const float*)d_in[0];
    const float* guide  = (const float*)d_in[1];
    const float* sp_dep = (const float*)d_in[2];
    const float* confid = (const float*)d_in[3];
    const float* conv_w = (const float*)d_in[4];
    const float* conv_b = (const float*)d_in[5];

    float* out = (float*)d_out;
    float* pred = out;
    float* feat = out + NPIX;
    float* inter = out + 2 * (size_t)NPIX;

    static bool attr_set = false;
    if (!attr_set) {
        cudaFuncSetAttribute(wino_kernel, cudaFuncAttributeMaxDynamicSharedMemorySize, SM_TOTAL);
        attr_set = true;
    }

    prep_kernel<<<(27 * 96 + 255) / 256, 256>>>(conv_w);

    dim3 wgrid(GX, GY, BB);
    wino_kernel<<<wgrid, 512, SM_TOTAL>>>(guide, conv_b);

    int pb = (NPIX + 255) / 256;
    prop_kernel<<<pb, 256>>>(input, sp_dep, confid, inter, nullptr, input, feat, 0);
    prop_kernel<<<pb, 256>>>(inter, sp_dep, confid, inter + NPIX, nullptr, nullptr, nullptr, 1);
    prop_kernel<<<pb, 256>>>(inter + NPIX, sp_dep, confid, inter + 2 * (size_t)NPIX, pred, nullptr, nullptr, 2);
}